// round 10
// baseline (speedup 1.0000x reference)
#include <cuda_runtime.h>
#include <cuda_fp16.h>
#include <math_constants.h>

// SumLayer: out[nids[n], b] = log(clip(sum_c params[pids[n,c]] * exp(em[cids[n,c],b]), 1e-10))
//
// Fused persistent kernel, batch split in halves of 128:
//   Stage A: phase1 half0 (scratch = half(exp(em)), fp16 table in L2)
//   Stage B: 2/5 blocks phase1 half1 (DRAM-bound)  ||  3/5 blocks phase2 half0 (LTS-bound)
//   Stage C: all blocks phase2 half1
// Grid sized via occupancy API so all blocks are co-resident -> software
// grid barrier (monotone generation counter, wrap-safe, never reset).

#define FAST_C 16
#define FAST_B 256
#define NPB 8                  // nodes per block (1 warp per node)
#define CH_SIZE_MAX 131072

// 64 MB scratch: exp(em) as half. uint2 units (4 halves); row stride = 64 uint2.
__device__ uint2 g_scratch[(size_t)CH_SIZE_MAX * 64];
__device__ unsigned g_bar;     // monotone barrier counter (never reset)

// ---- packed helpers ----
__device__ __forceinline__ unsigned long long h2_to_f32x2(unsigned int h)
{
    unsigned long long f;
    asm("{\n\t"
        ".reg .f16 a, b;\n\t"
        ".reg .f32 fa, fb;\n\t"
        "mov.b32 {a, b}, %1;\n\t"
        "cvt.f32.f16 fa, a;\n\t"
        "cvt.f32.f16 fb, b;\n\t"
        "mov.b64 %0, {fa, fb};\n\t"
        "}" : "=l"(f) : "r"(h));
    return f;
}

__device__ __forceinline__ void fma_f32x2(unsigned long long& acc,
                                          unsigned long long a,
                                          unsigned long long b)
{
    asm("fma.rn.f32x2 %0, %1, %2, %3;" : "=l"(acc) : "l"(a), "l"(b), "l"(acc));
}

// ---- grid barrier: generation-counting, wrap-safe, reusable across replays ----
__device__ __forceinline__ void grid_barrier(unsigned nblocks)
{
    __syncthreads();
    if (threadIdx.x == 0) {
        __threadfence();
        unsigned my = atomicAdd(&g_bar, 1u);
        unsigned target = (my / nblocks + 1u) * nblocks;
        while ((int)(*(volatile unsigned*)&g_bar - target) < 0) {
            __nanosleep(64);
        }
        __threadfence();
    }
    __syncthreads();
}

// ---- phase 1 over one batch half: scratch[row, half] = half(exp(em[row, half])) ----
__device__ __forceinline__ void p1_half(const float4* __restrict__ em4,
                                        int rows, int h, int worker, int nworkers)
{
    const int total = rows << 5;                 // rows * 32 float4 per half-row
    uint2* __restrict__ sc = g_scratch;
    for (int idx = worker * 256 + threadIdx.x; idx < total; idx += nworkers * 256) {
        const int row = idx >> 5, q = idx & 31;
        const int off = (row << 6) + (h << 5) + q;   // same linear index for em4/scratch
        float4 v = __ldcs(&em4[off]);
        __half2 h0 = __floats2half2_rn(__expf(v.x), __expf(v.y));
        __half2 h1 = __floats2half2_rn(__expf(v.z), __expf(v.w));
        uint2 u;
        ((__half2*)&u)[0] = h0;
        ((__half2*)&u)[1] = h1;
        sc[off] = u;                              // stays L2-resident for phase 2
    }
}

// ---- phase 2 over one batch half: warp per node, uint2 gathers (4 elems/lane) ----
__device__ __forceinline__ void p2_half(const float* __restrict__ params,
                                        const int* __restrict__ nids,
                                        const int* __restrict__ cids,
                                        const int* __restrict__ pids,
                                        float* __restrict__ out,
                                        int h, int worker, int nworkers, int ngroups,
                                        int* s_row_all, float2* s_w_all)
{
    const int w    = threadIdx.x >> 5;
    const int lane = threadIdx.x & 31;
    int*    s_row = s_row_all + w * FAST_C;
    float2* s_w   = s_w_all   + w * FAST_C;
    const uint2* __restrict__ sc = g_scratch;

    for (int g = worker; g < ngroups; g += nworkers) {
        const int node = (g << 3) + w;
        if (lane < FAST_C) {
            s_row[lane] = cids[(node << 4) + lane] << 6;       // uint2 row stride 64
            const float wv = params[pids[(node << 4) + lane]];
            s_w[lane] = make_float2(wv, wv);
        }
        __syncwarp();

        unsigned long long a0 = 0, a1 = 0;
#pragma unroll
        for (int ch = 0; ch < FAST_C; ch += 4) {
            uint2 v[4];
#pragma unroll
            for (int c = 0; c < 4; c++) {
                v[c] = sc[s_row[ch + c] + (h << 5) + lane];
            }
#pragma unroll
            for (int c = 0; c < 4; c++) {
                const unsigned long long wp =
                    *(const unsigned long long*)&s_w[ch + c];  // LDS.64 bcast
                fma_f32x2(a0, h2_to_f32x2(v[c].x), wp);
                fma_f32x2(a1, h2_to_f32x2(v[c].y), wp);
            }
        }

        const float2 s0 = *(float2*)&a0, s1 = *(float2*)&a1;
        float4 o;
        o.x = __logf(fmaxf(s0.x, 1e-10f));
        o.y = __logf(fmaxf(s0.y, 1e-10f));
        o.z = __logf(fmaxf(s1.x, 1e-10f));
        o.w = __logf(fmaxf(s1.y, 1e-10f));

        float4* orow = (float4*)out + ((long long)nids[node] << 6) + (h << 5);
        __stcs(&orow[lane], o);
        __syncwarp();                 // protect s_row/s_w before next iteration
    }
}

// ---- fused persistent kernel ----
__global__ __launch_bounds__(256, 5) void sum_layer_fused(
    const float4* __restrict__ em4,
    const float*  __restrict__ params,
    const int*    __restrict__ nids,
    const int*    __restrict__ cids,
    const int*    __restrict__ pids,
    float*        __restrict__ out,
    int rows, int ngroups, int nblocks, int g1)
{
    __shared__ int    s_row_all[NPB * FAST_C];
    __shared__ float2 s_w_all[NPB * FAST_C];

    const int bid = blockIdx.x;

    // Stage A: phase 1, half 0, all blocks
    p1_half(em4, rows, 0, bid, nblocks);
    grid_barrier((unsigned)nblocks);

    // Stage B: split
    if (bid < g1) {
        p1_half(em4, rows, 1, bid, g1);
    } else {
        p2_half(params, nids, cids, pids, out, 0,
                bid - g1, nblocks - g1, ngroups, s_row_all, s_w_all);
    }
    grid_barrier((unsigned)nblocks);

    // Stage C: phase 2, half 1, all blocks
    p2_half(params, nids, cids, pids, out, 1,
            bid, nblocks, ngroups, s_row_all, s_w_all);
}

// ---------------- Generic fallback (exact, single kernel) ----------------
__global__ void sum_layer_generic(
    const float* __restrict__ em,
    const float* __restrict__ params,
    const int*   __restrict__ nids,
    const int*   __restrict__ cids,
    const int*   __restrict__ pids,
    float*       __restrict__ out,
    int n_nodes, int C, int B)
{
    long long idx = (long long)blockIdx.x * blockDim.x + threadIdx.x;
    long long total = (long long)n_nodes * B;
    if (idx >= total) return;
    int node = (int)(idx / B);
    int b    = (int)(idx % B);

    float m = -CUDART_INF_F;
    for (int c = 0; c < C; c++) {
        float v = em[(long long)cids[node * C + c] * B + b];
        m = fmaxf(m, v);
    }
    float s = 0.f;
    for (int c = 0; c < C; c++) {
        float v = em[(long long)cids[node * C + c] * B + b];
        s += __expf(v - m) * params[pids[node * C + c]];
    }
    out[(long long)nids[node] * B + b] = __logf(fmaxf(s, 1e-10f)) + m;
}

extern "C" void kernel_launch(void* const* d_in, const int* in_sizes, int n_in,
                              void* d_out, int out_size)
{
    // metadata order: node_mars, element_mars, params, nids, cids, pids
    const float* em     = (const float*)d_in[1];
    const float* params = (const float*)d_in[2];
    const int*   nids   = (const int*)d_in[3];
    const int*   cids   = (const int*)d_in[4];
    const int*   pids   = (const int*)d_in[5];
    float*       out    = (float*)d_out;

    const int n_nodes = in_sizes[3];
    const int C       = in_sizes[4] / n_nodes;
    const int B       = in_sizes[0] / n_nodes;
    const int ch_size = in_sizes[1] / B;      // element_mars rows

    int bpm = 0, sms = 0, dev = 0;
    cudaGetDevice(&dev);
    cudaOccupancyMaxActiveBlocksPerMultiprocessor(&bpm, sum_layer_fused, 256, 0);
    cudaDeviceGetAttribute(&sms, cudaDevAttrMultiProcessorCount, dev);

    if (C == FAST_C && B == FAST_B && (n_nodes % NPB) == 0 &&
        ch_size <= CH_SIZE_MAX && bpm >= 1 && sms >= 1) {
        const int nblocks = bpm * sms;             // guaranteed co-resident
        const int ngroups = n_nodes / NPB;
        int g1 = (2 * nblocks) / 5;                // stage-B phase-1 workers
        if (g1 < 1) g1 = 1;
        if (g1 >= nblocks) g1 = nblocks - 1;
        sum_layer_fused<<<nblocks, 256>>>((const float4*)em, params, nids, cids,
                                          pids, out, ch_size, ngroups, nblocks, g1);
    } else {
        const long long total = (long long)n_nodes * B;
        const int threads = 256;
        const int grid = (int)((total + threads - 1) / threads);
        sum_layer_generic<<<grid, threads>>>(em, params, nids, cids, pids, out,
                                             n_nodes, C, B);
    }
}